// round 6
// baseline (speedup 1.0000x reference)
#include <cuda_runtime.h>

#define NXMAX (1 << 20)
#define BLK 256
#define NSTEPS 32

// Double-buffered conserved state (static scratch; no runtime allocation).
__device__ float g_r[2][NXMAX];
__device__ float g_m[2][NXMAX];
__device__ float g_e[2][NXMAX];
__device__ unsigned int g_maxbits;   // running max of |u|+c (positive float bits)
__device__ unsigned int g_count;     // last-block-finish counter
__device__ float g_t;
__device__ float g_dtdx;

__global__ void pre_kernel() {
    g_maxbits = 0u;
    g_count = 0u;
    g_t = 0.0f;
}

// Fast sqrt via single MUFU.RSQ (args are strictly positive here).
__device__ __forceinline__ float fsqrt_fast(float x) { return x * rsqrtf(x); }

struct Cell { float r, m, E, u, p, q, H; };

__device__ __forceinline__ Cell derive(float r, float m, float E) {
    Cell c;
    float s = rsqrtf(r);      // 1/sqrt(r)
    float ir = s * s;         // ~1/r
    c.r = r; c.m = m; c.E = E;
    c.u = m * ir;
    c.p = 0.4f * (E - 0.5f * m * c.u);
    c.q = r * s;              // sqrt(r)
    c.H = (E + c.p) * ir;
    return c;
}

// Roe flux with Harten entropy fix.
__device__ __forceinline__ float3 roe_flux(const Cell& L, const Cell& R) {
    float rd = __fdividef(1.0f, L.q + R.q);
    float ur = (L.q * L.u + R.q * R.u) * rd;
    float Hr = (L.q * L.H + R.q * R.H) * rd;
    float c2 = fmaxf(0.4f * (Hr - 0.5f * ur * ur), 1e-10f);
    float cinv = rsqrtf(c2);
    float c = c2 * cinv;
    float ic2 = cinv * cinv;
    float e2 = 0.01f * c2;                      // (0.1*c)^2
    float l1 = ur - c, l3 = ur + c;
    float a1 = fsqrt_fast(l1 * l1 + e2);
    float a2 = fsqrt_fast(ur * ur + e2);
    float a3 = fsqrt_fast(l3 * l3 + e2);

    float drho = R.r - L.r, du = R.u - L.u, dp = R.p - L.p;
    float h = 0.5f * ic2;
    float crdu = c * R.r * du;
    float b1 = a1 * ((dp - crdu) * h);
    float b3 = a3 * ((dp + crdu) * h);
    float b2 = a2 * (drho - dp * ic2);
    float uc = ur * c;

    float3 F;
    F.x = 0.5f * (L.m + R.m - (b1 + b2 + b3));
    F.y = 0.5f * ((L.m * L.u + L.p) + (R.m * R.u + R.p)
                  - (b1 * l1 + b2 * ur + b3 * l3));
    F.z = 0.5f * (L.u * (L.E + L.p) + R.u * (R.E + R.p)
                  - (b1 * (Hr - uc) + b2 * (0.5f * ur * ur) + b3 * (Hr + uc)));
    return F;
}

// Block max-reduce of spd, atomicMax into g_maxbits, and last-finishing block
// computes the NEXT step's dt (threadFenceReduction pattern).
__device__ __forceinline__ void reduce_and_dt(float spd, const float* tf) {
    unsigned int bits = __float_as_uint(spd);
    bits = __reduce_max_sync(0xffffffffu, bits);
    __shared__ unsigned int swm[BLK / 32];
    int tid = threadIdx.x;
    if ((tid & 31) == 0) swm[tid >> 5] = bits;
    __syncthreads();
    if (tid == 0) {
        unsigned int m = swm[0];
#pragma unroll
        for (int w = 1; w < BLK / 32; w++) m = max(m, swm[w]);
        atomicMax(&g_maxbits, m);
        __threadfence();
        unsigned int old = atomicAdd(&g_count, 1u);
        if (old == gridDim.x - 1) {
            // All blocks done: their atomicMax results are visible.
            float mx = __uint_as_float(g_maxbits);
            float dt = 5e-4f / mx;                      // CFL*DX / max
            float rem = fmaxf(*tf - g_t, 0.0f);
            dt = fminf(dt, rem);
            g_t += dt;
            g_dtdx = dt * 1000.0f;                      // dt / DX
            g_maxbits = 0u;
            g_count = 0u;
            __threadfence();
        }
    }
}

// Primitives -> conserved, reduce initial max wavespeed, last block computes dt0.
__global__ void __launch_bounds__(BLK) init_kernel(
    const float* __restrict__ rho, const float* __restrict__ u,
    const float* __restrict__ p, const float* __restrict__ tf, int n) {
    int i0 = (blockIdx.x * BLK + threadIdx.x) * 4;
    float4 r4 = *reinterpret_cast<const float4*>(rho + i0);
    float4 u4 = *reinterpret_cast<const float4*>(u + i0);
    float4 p4 = *reinterpret_cast<const float4*>(p + i0);
    float rr[4] = {r4.x, r4.y, r4.z, r4.w};
    float uu[4] = {u4.x, u4.y, u4.z, u4.w};
    float pp[4] = {p4.x, p4.y, p4.z, p4.w};
    float mm[4], ee[4];
    float spd = 0.0f;
#pragma unroll
    for (int k = 0; k < 4; k++) {
        mm[k] = rr[k] * uu[k];
        ee[k] = pp[k] * 2.5f + 0.5f * mm[k] * uu[k];
        float s = rsqrtf(rr[k]);
        float ir = s * s;
        spd = fmaxf(spd, fabsf(uu[k]) + fsqrt_fast(1.4f * pp[k] * ir));
    }
    *reinterpret_cast<float4*>(g_r[0] + i0) = make_float4(rr[0], rr[1], rr[2], rr[3]);
    *reinterpret_cast<float4*>(g_m[0] + i0) = make_float4(mm[0], mm[1], mm[2], mm[3]);
    *reinterpret_cast<float4*>(g_e[0] + i0) = make_float4(ee[0], ee[1], ee[2], ee[3]);
    reduce_and_dt(spd, tf);
}

// One Euler step: 4 cells/thread, fluxes in registers, boundary flux via
// shfl_up (warp interior), shared staging at warp boundaries, recompute at
// block boundary (1 thread per block). Fused new-state max reduction + dt.
template <bool LAST>
__global__ void __launch_bounds__(BLK) flux_kernel(
    int src, float* __restrict__ prim_out, const float* __restrict__ tf, int n) {
    const float* __restrict__ r_in = g_r[src];
    const float* __restrict__ m_in = g_m[src];
    const float* __restrict__ e_in = g_e[src];
    float* __restrict__ r_out = g_r[src ^ 1];
    float* __restrict__ m_out = g_m[src ^ 1];
    float* __restrict__ e_out = g_e[src ^ 1];

    const int tid = threadIdx.x;
    const int lane = tid & 31;
    const int warp = tid >> 5;
    const int i0 = (blockIdx.x * BLK + tid) * 4;

    float4 r4 = *reinterpret_cast<const float4*>(r_in + i0);
    float4 m4 = *reinterpret_cast<const float4*>(m_in + i0);
    float4 e4 = *reinterpret_cast<const float4*>(e_in + i0);
    int iR = min(i0 + 4, n - 1);              // right ghost replicate at domain end

    Cell cell[5];
    cell[0] = derive(r4.x, m4.x, e4.x);
    cell[1] = derive(r4.y, m4.y, e4.y);
    cell[2] = derive(r4.z, m4.z, e4.z);
    cell[3] = derive(r4.w, m4.w, e4.w);
    cell[4] = derive(r_in[iR], m_in[iR], e_in[iR]);

    float3 F[5];
#pragma unroll
    for (int k = 1; k < 5; k++) F[k] = roe_flux(cell[k - 1], cell[k]);

    // Pass F[4] to the right-neighbor thread as its F[0].
    __shared__ float3 s_bound[BLK / 32];
    if (lane == 31) s_bound[warp] = F[4];
    __syncthreads();
    F[0].x = __shfl_up_sync(0xffffffffu, F[4].x, 1);
    F[0].y = __shfl_up_sync(0xffffffffu, F[4].y, 1);
    F[0].z = __shfl_up_sync(0xffffffffu, F[4].z, 1);
    if (lane == 0) {
        if (warp > 0) {
            F[0] = s_bound[warp - 1];
        } else {
            int iL = max(i0 - 1, 0);          // left ghost replicate at domain start
            Cell cl = derive(r_in[iL], m_in[iL], e_in[iL]);
            F[0] = roe_flux(cl, cell[0]);
        }
    }

    const float dtdx = g_dtdx;
    float nr[4], nm[4], ne[4];
#pragma unroll
    for (int k = 0; k < 4; k++) {
        nr[k] = cell[k].r - dtdx * (F[k + 1].x - F[k].x);
        nm[k] = cell[k].m - dtdx * (F[k + 1].y - F[k].y);
        ne[k] = cell[k].E - dtdx * (F[k + 1].z - F[k].z);
    }

    if (LAST) {
        float nu[4], np[4];
#pragma unroll
        for (int k = 0; k < 4; k++) {
            float s = rsqrtf(nr[k]);
            float inr = s * s;
            nu[k] = nm[k] * inr;
            np[k] = 0.4f * (ne[k] - 0.5f * nm[k] * nu[k]);
        }
        *reinterpret_cast<float4*>(prim_out + i0) = make_float4(nr[0], nr[1], nr[2], nr[3]);
        *reinterpret_cast<float4*>(prim_out + n + i0) = make_float4(nu[0], nu[1], nu[2], nu[3]);
        *reinterpret_cast<float4*>(prim_out + 2 * n + i0) = make_float4(np[0], np[1], np[2], np[3]);
    } else {
        *reinterpret_cast<float4*>(r_out + i0) = make_float4(nr[0], nr[1], nr[2], nr[3]);
        *reinterpret_cast<float4*>(m_out + i0) = make_float4(nm[0], nm[1], nm[2], nm[3]);
        *reinterpret_cast<float4*>(e_out + i0) = make_float4(ne[0], ne[1], ne[2], ne[3]);
        float spd = 0.0f;
#pragma unroll
        for (int k = 0; k < 4; k++) {
            float s = rsqrtf(nr[k]);
            float inr = s * s;
            float nu = nm[k] * inr;
            float np = 0.4f * (ne[k] - 0.5f * nm[k] * nu);
            spd = fmaxf(spd, fabsf(nu) + fsqrt_fast(1.4f * np * inr));
        }
        __syncthreads();   // protect s_bound reuse ordering vs swm in reduce
        reduce_and_dt(spd, tf);
    }
}

extern "C" void kernel_launch(void* const* d_in, const int* in_sizes, int n_in,
                              void* d_out, int out_size) {
    const float* rho = (const float*)d_in[0];
    const float* u = (const float*)d_in[1];
    const float* p = (const float*)d_in[2];
    const float* tf = (const float*)d_in[3];
    float* out = (float*)d_out;
    int n = in_sizes[0];
    if (n > NXMAX || (n & 1023)) return;      // expect n = 2^20 (mult of 4*BLK)
    int nblk = n / (4 * BLK);

    pre_kernel<<<1, 1>>>();
    init_kernel<<<nblk, BLK>>>(rho, u, p, tf, n);
    for (int s = 0; s < NSTEPS; s++) {
        if (s < NSTEPS - 1)
            flux_kernel<false><<<nblk, BLK>>>(s & 1, nullptr, tf, n);
        else
            flux_kernel<true><<<nblk, BLK>>>(s & 1, out, tf, n);
    }
}

// round 7
// speedup vs baseline: 1.0086x; 1.0086x over previous
#include <cuda_runtime.h>

#define NXMAX (1 << 20)
#define BLK 256
#define NSTEPS 32

// Double-buffered conserved state (static scratch; no runtime allocation).
__device__ float g_r[2][NXMAX];
__device__ float g_m[2][NXMAX];
__device__ float g_e[2][NXMAX];
__device__ unsigned int g_maxbits;   // running max of |u|+c (positive float bits)
__device__ unsigned int g_count;     // last-block-finish counter
__device__ float g_t;
__device__ float g_dtdx;

__global__ void pre_kernel() {
    g_maxbits = 0u;
    g_count = 0u;
    g_t = 0.0f;
}

// Fast sqrt via single MUFU.RSQ (args are strictly positive here).
__device__ __forceinline__ float fsqrt_fast(float x) { return x * rsqrtf(x); }

struct Cell { float r, m, E, u, p, q, H; };

__device__ __forceinline__ Cell derive(float r, float m, float E) {
    Cell c;
    float s = rsqrtf(r);      // 1/sqrt(r)
    float ir = s * s;         // ~1/r
    c.r = r; c.m = m; c.E = E;
    c.u = m * ir;
    c.p = 0.4f * (E - 0.5f * m * c.u);
    c.q = r * s;              // sqrt(r)
    c.H = (E + c.p) * ir;
    return c;
}

// Roe flux with Harten entropy fix.
__device__ __forceinline__ float3 roe_flux(const Cell& L, const Cell& R) {
    float rd = __fdividef(1.0f, L.q + R.q);
    float ur = (L.q * L.u + R.q * R.u) * rd;
    float Hr = (L.q * L.H + R.q * R.H) * rd;
    float c2 = fmaxf(0.4f * (Hr - 0.5f * ur * ur), 1e-10f);
    float cinv = rsqrtf(c2);
    float c = c2 * cinv;
    float ic2 = cinv * cinv;
    float e2 = 0.01f * c2;                      // (0.1*c)^2
    float l1 = ur - c, l3 = ur + c;
    float a1 = fsqrt_fast(l1 * l1 + e2);
    float a2 = fsqrt_fast(ur * ur + e2);
    float a3 = fsqrt_fast(l3 * l3 + e2);

    float drho = R.r - L.r, du = R.u - L.u, dp = R.p - L.p;
    float h = 0.5f * ic2;
    float crdu = c * R.r * du;
    float b1 = a1 * ((dp - crdu) * h);
    float b3 = a3 * ((dp + crdu) * h);
    float b2 = a2 * (drho - dp * ic2);
    float uc = ur * c;

    float3 F;
    F.x = 0.5f * (L.m + R.m - (b1 + b2 + b3));
    F.y = 0.5f * ((L.m * L.u + L.p) + (R.m * R.u + R.p)
                  - (b1 * l1 + b2 * ur + b3 * l3));
    F.z = 0.5f * (L.u * (L.E + L.p) + R.u * (R.E + R.p)
                  - (b1 * (Hr - uc) + b2 * (0.5f * ur * ur) + b3 * (Hr + uc)));
    return F;
}

// Block max-reduce of spd, atomicMax into g_maxbits, and last-finishing block
// computes the NEXT step's dt (threadFenceReduction pattern).
__device__ __forceinline__ void reduce_and_dt(float spd, const float* tf) {
    unsigned int bits = __float_as_uint(spd);
    bits = __reduce_max_sync(0xffffffffu, bits);
    __shared__ unsigned int swm[BLK / 32];
    int tid = threadIdx.x;
    if ((tid & 31) == 0) swm[tid >> 5] = bits;
    __syncthreads();
    if (tid == 0) {
        unsigned int m = swm[0];
#pragma unroll
        for (int w = 1; w < BLK / 32; w++) m = max(m, swm[w]);
        atomicMax(&g_maxbits, m);
        __threadfence();
        unsigned int old = atomicAdd(&g_count, 1u);
        if (old == gridDim.x - 1) {
            // All blocks done: their atomicMax results are visible.
            float mx = __uint_as_float(g_maxbits);
            float dt = 5e-4f / mx;                      // CFL*DX / max
            float rem = fmaxf(*tf - g_t, 0.0f);
            dt = fminf(dt, rem);
            g_t += dt;
            g_dtdx = dt * 1000.0f;                      // dt / DX
            g_maxbits = 0u;
            g_count = 0u;
            __threadfence();
        }
    }
}

// Primitives -> conserved, reduce initial max wavespeed, last block computes dt0.
__global__ void __launch_bounds__(BLK) init_kernel(
    const float* __restrict__ rho, const float* __restrict__ u,
    const float* __restrict__ p, const float* __restrict__ tf, int n) {
    int i0 = (blockIdx.x * BLK + threadIdx.x) * 4;
    float4 r4 = *reinterpret_cast<const float4*>(rho + i0);
    float4 u4 = *reinterpret_cast<const float4*>(u + i0);
    float4 p4 = *reinterpret_cast<const float4*>(p + i0);
    float rr[4] = {r4.x, r4.y, r4.z, r4.w};
    float uu[4] = {u4.x, u4.y, u4.z, u4.w};
    float pp[4] = {p4.x, p4.y, p4.z, p4.w};
    float mm[4], ee[4];
    float spd = 0.0f;
#pragma unroll
    for (int k = 0; k < 4; k++) {
        mm[k] = rr[k] * uu[k];
        ee[k] = pp[k] * 2.5f + 0.5f * mm[k] * uu[k];
        float s = rsqrtf(rr[k]);
        float ir = s * s;
        spd = fmaxf(spd, fabsf(uu[k]) + fsqrt_fast(1.4f * pp[k] * ir));
    }
    *reinterpret_cast<float4*>(g_r[0] + i0) = make_float4(rr[0], rr[1], rr[2], rr[3]);
    *reinterpret_cast<float4*>(g_m[0] + i0) = make_float4(mm[0], mm[1], mm[2], mm[3]);
    *reinterpret_cast<float4*>(g_e[0] + i0) = make_float4(ee[0], ee[1], ee[2], ee[3]);
    reduce_and_dt(spd, tf);
}

// One Euler step: 4 cells/thread, fluxes in registers, boundary flux via
// shfl_up (warp interior), shared staging at warp boundaries, recompute at
// block boundary (1 thread per block). Fused new-state max reduction + dt.
template <bool LAST>
__global__ void __launch_bounds__(BLK) flux_kernel(
    int src, float* __restrict__ prim_out, const float* __restrict__ tf, int n) {
    const float* __restrict__ r_in = g_r[src];
    const float* __restrict__ m_in = g_m[src];
    const float* __restrict__ e_in = g_e[src];
    float* __restrict__ r_out = g_r[src ^ 1];
    float* __restrict__ m_out = g_m[src ^ 1];
    float* __restrict__ e_out = g_e[src ^ 1];

    const int tid = threadIdx.x;
    const int lane = tid & 31;
    const int warp = tid >> 5;
    const int i0 = (blockIdx.x * BLK + tid) * 4;

    float4 r4 = *reinterpret_cast<const float4*>(r_in + i0);
    float4 m4 = *reinterpret_cast<const float4*>(m_in + i0);
    float4 e4 = *reinterpret_cast<const float4*>(e_in + i0);
    int iR = min(i0 + 4, n - 1);              // right ghost replicate at domain end

    Cell cell[5];
    cell[0] = derive(r4.x, m4.x, e4.x);
    cell[1] = derive(r4.y, m4.y, e4.y);
    cell[2] = derive(r4.z, m4.z, e4.z);
    cell[3] = derive(r4.w, m4.w, e4.w);
    cell[4] = derive(r_in[iR], m_in[iR], e_in[iR]);

    float3 F[5];
#pragma unroll
    for (int k = 1; k < 5; k++) F[k] = roe_flux(cell[k - 1], cell[k]);

    // Pass F[4] to the right-neighbor thread as its F[0].
    __shared__ float3 s_bound[BLK / 32];
    if (lane == 31) s_bound[warp] = F[4];
    __syncthreads();
    F[0].x = __shfl_up_sync(0xffffffffu, F[4].x, 1);
    F[0].y = __shfl_up_sync(0xffffffffu, F[4].y, 1);
    F[0].z = __shfl_up_sync(0xffffffffu, F[4].z, 1);
    if (lane == 0) {
        if (warp > 0) {
            F[0] = s_bound[warp - 1];
        } else {
            int iL = max(i0 - 1, 0);          // left ghost replicate at domain start
            Cell cl = derive(r_in[iL], m_in[iL], e_in[iL]);
            F[0] = roe_flux(cl, cell[0]);
        }
    }

    const float dtdx = g_dtdx;
    float nr[4], nm[4], ne[4];
#pragma unroll
    for (int k = 0; k < 4; k++) {
        nr[k] = cell[k].r - dtdx * (F[k + 1].x - F[k].x);
        nm[k] = cell[k].m - dtdx * (F[k + 1].y - F[k].y);
        ne[k] = cell[k].E - dtdx * (F[k + 1].z - F[k].z);
    }

    if (LAST) {
        float nu[4], np[4];
#pragma unroll
        for (int k = 0; k < 4; k++) {
            float s = rsqrtf(nr[k]);
            float inr = s * s;
            nu[k] = nm[k] * inr;
            np[k] = 0.4f * (ne[k] - 0.5f * nm[k] * nu[k]);
        }
        *reinterpret_cast<float4*>(prim_out + i0) = make_float4(nr[0], nr[1], nr[2], nr[3]);
        *reinterpret_cast<float4*>(prim_out + n + i0) = make_float4(nu[0], nu[1], nu[2], nu[3]);
        *reinterpret_cast<float4*>(prim_out + 2 * n + i0) = make_float4(np[0], np[1], np[2], np[3]);
    } else {
        *reinterpret_cast<float4*>(r_out + i0) = make_float4(nr[0], nr[1], nr[2], nr[3]);
        *reinterpret_cast<float4*>(m_out + i0) = make_float4(nm[0], nm[1], nm[2], nm[3]);
        *reinterpret_cast<float4*>(e_out + i0) = make_float4(ne[0], ne[1], ne[2], ne[3]);
        float spd = 0.0f;
#pragma unroll
        for (int k = 0; k < 4; k++) {
            float s = rsqrtf(nr[k]);
            float inr = s * s;
            float nu = nm[k] * inr;
            float np = 0.4f * (ne[k] - 0.5f * nm[k] * nu);
            spd = fmaxf(spd, fabsf(nu) + fsqrt_fast(1.4f * np * inr));
        }
        __syncthreads();   // protect s_bound reuse ordering vs swm in reduce
        reduce_and_dt(spd, tf);
    }
}

extern "C" void kernel_launch(void* const* d_in, const int* in_sizes, int n_in,
                              void* d_out, int out_size) {
    const float* rho = (const float*)d_in[0];
    const float* u = (const float*)d_in[1];
    const float* p = (const float*)d_in[2];
    const float* tf = (const float*)d_in[3];
    float* out = (float*)d_out;
    int n = in_sizes[0];
    if (n > NXMAX || (n & 1023)) return;      // expect n = 2^20 (mult of 4*BLK)
    int nblk = n / (4 * BLK);

    pre_kernel<<<1, 1>>>();
    init_kernel<<<nblk, BLK>>>(rho, u, p, tf, n);
    for (int s = 0; s < NSTEPS; s++) {
        if (s < NSTEPS - 1)
            flux_kernel<false><<<nblk, BLK>>>(s & 1, nullptr, tf, n);
        else
            flux_kernel<true><<<nblk, BLK>>>(s & 1, out, tf, n);
    }
}

// round 8
// speedup vs baseline: 1.0841x; 1.0749x over previous
#include <cuda_runtime.h>

#define TPB 1024
#define CPT 8                       // cells per thread
#define NBLK 128                    // 128 blocks <= 148 SMs -> all co-resident
#define NXFIX (TPB * CPT * NBLK)    // 1<<20
#define NSTEPS 32

// Block-edge halos (r,m,E,pad), double-buffered by step parity.
__device__ float4 g_haloL[2][NBLK];   // block b's first cell
__device__ float4 g_haloR[2][NBLK];   // block b's last cell
__device__ unsigned int g_maxbits;    // running max |u|+c (positive float bits)
__device__ unsigned int g_arrive;     // grid barrier arrival counter
__device__ volatile unsigned int g_release;  // grid barrier release epoch
__device__ float g_t;
__device__ float g_dtdx;

__global__ void pre_kernel() {
    g_maxbits = 0u;
    g_arrive = 0u;
    g_release = 0u;
    g_t = 0.0f;
}

__device__ __forceinline__ float fsqrt_fast(float x) { return x * rsqrtf(x); }

struct Cell { float r, m, E, u, p, q, H; };

__device__ __forceinline__ Cell derive(float r, float m, float E) {
    Cell c;
    float s = rsqrtf(r);
    float ir = s * s;
    c.r = r; c.m = m; c.E = E;
    c.u = m * ir;
    c.p = 0.4f * (E - 0.5f * m * c.u);
    c.q = r * s;
    c.H = (E + c.p) * ir;
    return c;
}

// Roe flux with Harten entropy fix.
__device__ __forceinline__ float3 roe_flux(const Cell& L, const Cell& R) {
    float rd = __fdividef(1.0f, L.q + R.q);
    float ur = (L.q * L.u + R.q * R.u) * rd;
    float Hr = (L.q * L.H + R.q * R.H) * rd;
    float c2 = fmaxf(0.4f * (Hr - 0.5f * ur * ur), 1e-10f);
    float cinv = rsqrtf(c2);
    float c = c2 * cinv;
    float ic2 = cinv * cinv;
    float e2 = 0.01f * c2;
    float l1 = ur - c, l3 = ur + c;
    float a1 = fsqrt_fast(l1 * l1 + e2);
    float a2 = fsqrt_fast(ur * ur + e2);
    float a3 = fsqrt_fast(l3 * l3 + e2);

    float drho = R.r - L.r, du = R.u - L.u, dp = R.p - L.p;
    float h = 0.5f * ic2;
    float crdu = c * R.r * du;
    float b1 = a1 * ((dp - crdu) * h);
    float b3 = a3 * ((dp + crdu) * h);
    float b2 = a2 * (drho - dp * ic2);
    float uc = ur * c;

    float3 F;
    F.x = 0.5f * (L.m + R.m - (b1 + b2 + b3));
    F.y = 0.5f * ((L.m * L.u + L.p) + (R.m * R.u + R.p)
                  - (b1 * l1 + b2 * ur + b3 * l3));
    F.z = 0.5f * (L.u * (L.E + L.p) + R.u * (R.E + R.p)
                  - (b1 * (Hr - uc) + b2 * (0.5f * ur * ur) + b3 * (Hr + uc)));
    return F;
}

__device__ __forceinline__ float wavespd(float r, float m, float E) {
    float s = rsqrtf(r);
    float ir = s * s;
    float u = m * ir;
    float p = 0.4f * (E - 0.5f * m * u);
    return fabsf(u) + fsqrt_fast(1.4f * p * ir);
}

// Block max-reduce + grid-wide barrier; last-arriving block computes next dt.
__device__ __forceinline__ void grid_barrier_dt(float spd, const float* tf,
                                                unsigned int epoch,
                                                unsigned int* swm) {
    int tid = threadIdx.x;
    unsigned int bits = __float_as_uint(spd);
    bits = __reduce_max_sync(0xffffffffu, bits);
    if ((tid & 31) == 0) swm[tid >> 5] = bits;
    __syncthreads();
    if (tid == 0) {
        unsigned int m = swm[0];
#pragma unroll
        for (int w = 1; w < TPB / 32; w++) m = max(m, swm[w]);
        atomicMax(&g_maxbits, m);
        __threadfence();
        unsigned int a = atomicAdd(&g_arrive, 1u);
        if (a == NBLK - 1) {
            // Everyone has arrived: their halos/atomicMax are visible.
            float mx = __uint_as_float(g_maxbits);
            float t = *(volatile float*)&g_t;
            float dt = fminf(5e-4f / mx, fmaxf(__ldcg(tf) - t, 0.0f));
            *(volatile float*)&g_t = t + dt;
            *(volatile float*)&g_dtdx = dt * 1000.0f;
            g_maxbits = 0u;
            g_arrive = 0u;
            __threadfence();
            g_release = epoch;           // volatile store -> release
        } else {
            while (g_release < epoch) {} // volatile spin
        }
        __threadfence();
    }
    __syncthreads();
}

__global__ void __launch_bounds__(TPB, 1) euler_kernel(
    const float* __restrict__ rho, const float* __restrict__ uin,
    const float* __restrict__ pin, const float* __restrict__ tf,
    float* __restrict__ out, int n) {
    // Per-thread edge exchange: derived of each thread's LAST cell (SoA, 7 arrays)
    __shared__ float sd_r[TPB], sd_m[TPB], sd_E[TPB], sd_u[TPB],
                     sd_p[TPB], sd_q[TPB], sd_H[TPB];
    // Each thread's FIRST flux (F at left face of its first cell)
    __shared__ float sf_x[TPB], sf_y[TPB], sf_z[TPB];
    __shared__ unsigned int swm[TPB / 32];

    const int tid = threadIdx.x;
    const int b = blockIdx.x;
    const int i0 = (b * TPB + tid) * CPT;

    // ---- init: primitives -> conserved (registers), initial halos + spd ----
    float r[CPT], m[CPT], E[CPT];
    {
        float spd = 0.0f;
#pragma unroll
        for (int h = 0; h < 2; h++) {
            float4 r4 = *reinterpret_cast<const float4*>(rho + i0 + 4 * h);
            float4 u4 = *reinterpret_cast<const float4*>(uin + i0 + 4 * h);
            float4 p4 = *reinterpret_cast<const float4*>(pin + i0 + 4 * h);
            float rr[4] = {r4.x, r4.y, r4.z, r4.w};
            float uu[4] = {u4.x, u4.y, u4.z, u4.w};
            float pp[4] = {p4.x, p4.y, p4.z, p4.w};
#pragma unroll
            for (int j = 0; j < 4; j++) {
                int k = 4 * h + j;
                r[k] = rr[j];
                m[k] = rr[j] * uu[j];
                E[k] = pp[j] * 2.5f + 0.5f * m[k] * uu[j];
                float s = rsqrtf(rr[j]);
                spd = fmaxf(spd, fabsf(uu[j]) + fsqrt_fast(1.4f * pp[j] * s * s));
            }
        }
        if (tid == 0) {
            __stcg(&g_haloL[0][b], make_float4(r[0], m[0], E[0], 0.0f));
            __threadfence();
        }
        if (tid == TPB - 1) {
            __stcg(&g_haloR[0][b], make_float4(r[CPT - 1], m[CPT - 1], E[CPT - 1], 0.0f));
            __threadfence();
        }
        grid_barrier_dt(spd, tf, 1u, swm);   // -> g_dtdx for step 0
    }

    // ---- 32 persistent steps ----
    for (int s = 0; s < NSTEPS; s++) {
        const float dtdx = __ldcg(&g_dtdx);
        const int rb = s & 1;

        // Prefetch old block-edge ghost states (edge threads only).
        float4 gl = make_float4(0, 0, 0, 0), gr = make_float4(0, 0, 0, 0);
        if (tid == 0 && b > 0)          gl = __ldcg(&g_haloR[rb][b - 1]);
        if (tid == TPB - 1 && b < NBLK - 1) gr = __ldcg(&g_haloL[rb][b + 1]);

        // Exchange derived of last cell with right-neighbor thread.
        Cell dlast = derive(r[CPT - 1], m[CPT - 1], E[CPT - 1]);
        sd_r[tid] = dlast.r; sd_m[tid] = dlast.m; sd_E[tid] = dlast.E;
        sd_u[tid] = dlast.u; sd_p[tid] = dlast.p; sd_q[tid] = dlast.q;
        sd_H[tid] = dlast.H;
        __syncthreads();

        Cell dl;
        Cell d0 = derive(r[0], m[0], E[0]);
        if (tid > 0) {
            int j = tid - 1;
            dl.r = sd_r[j]; dl.m = sd_m[j]; dl.E = sd_E[j]; dl.u = sd_u[j];
            dl.p = sd_p[j]; dl.q = sd_q[j]; dl.H = sd_H[j];
        } else if (b > 0) {
            dl = derive(gl.x, gl.y, gl.z);
        } else {
            dl = d0;                      // domain-left replicated ghost
        }
        float3 F0 = roe_flux(dl, d0);
        sf_x[tid] = F0.x; sf_y[tid] = F0.y; sf_z[tid] = F0.z;

        // Streaming fluxes + in-place updates for cells 0..CPT-2.
        Cell dp_ = d0;
        float3 Fp = F0;
#pragma unroll
        for (int k = 1; k < CPT; k++) {
            Cell dk = derive(r[k], m[k], E[k]);
            float3 Fk = roe_flux(dp_, dk);
            r[k - 1] -= dtdx * (Fk.x - Fp.x);
            m[k - 1] -= dtdx * (Fk.y - Fp.y);
            E[k - 1] -= dtdx * (Fk.z - Fp.z);
            dp_ = dk;
            Fp = Fk;
        }
        __syncthreads();

        // Flux at right face of last cell: neighbor thread's F0, or ghost roe.
        float3 F8;
        if (tid < TPB - 1) {
            F8.x = sf_x[tid + 1]; F8.y = sf_y[tid + 1]; F8.z = sf_z[tid + 1];
        } else {
            Cell dg = (b < NBLK - 1) ? derive(gr.x, gr.y, gr.z) : dp_;
            F8 = roe_flux(dp_, dg);
        }
        r[CPT - 1] -= dtdx * (F8.x - Fp.x);
        m[CPT - 1] -= dtdx * (F8.y - Fp.y);
        E[CPT - 1] -= dtdx * (F8.z - Fp.z);

        if (s + 1 < NSTEPS) {
            // Publish new block-edge halos into the other parity buffer.
            if (tid == 0) {
                __stcg(&g_haloL[rb ^ 1][b], make_float4(r[0], m[0], E[0], 0.0f));
                __threadfence();
            }
            if (tid == TPB - 1) {
                __stcg(&g_haloR[rb ^ 1][b],
                       make_float4(r[CPT - 1], m[CPT - 1], E[CPT - 1], 0.0f));
                __threadfence();
            }
            // New-state wavespeed for next dt, then grid-wide barrier.
            float spd = 0.0f;
#pragma unroll
            for (int k = 0; k < CPT; k++)
                spd = fmaxf(spd, wavespd(r[k], m[k], E[k]));
            grid_barrier_dt(spd, tf, (unsigned int)(s + 2), swm);
        }
    }

    // ---- final: conserved -> primitives, vectorized store ----
#pragma unroll
    for (int h = 0; h < 2; h++) {
        float nr[4], nu[4], np[4];
#pragma unroll
        for (int j = 0; j < 4; j++) {
            int k = 4 * h + j;
            float srr = rsqrtf(r[k]);
            float inr = srr * srr;
            nr[j] = r[k];
            nu[j] = m[k] * inr;
            np[j] = 0.4f * (E[k] - 0.5f * m[k] * nu[j]);
        }
        *reinterpret_cast<float4*>(out + i0 + 4 * h) =
            make_float4(nr[0], nr[1], nr[2], nr[3]);
        *reinterpret_cast<float4*>(out + n + i0 + 4 * h) =
            make_float4(nu[0], nu[1], nu[2], nu[3]);
        *reinterpret_cast<float4*>(out + 2 * n + i0 + 4 * h) =
            make_float4(np[0], np[1], np[2], np[3]);
    }
}

extern "C" void kernel_launch(void* const* d_in, const int* in_sizes, int n_in,
                              void* d_out, int out_size) {
    const float* rho = (const float*)d_in[0];
    const float* u = (const float*)d_in[1];
    const float* p = (const float*)d_in[2];
    const float* tf = (const float*)d_in[3];
    float* out = (float*)d_out;
    int n = in_sizes[0];
    if (n != NXFIX) return;   // problem is fixed at NX = 2^20

    pre_kernel<<<1, 1>>>();
    euler_kernel<<<NBLK, TPB>>>(rho, u, p, tf, out, n);
}

// round 9
// speedup vs baseline: 1.2558x; 1.1584x over previous
#include <cuda_runtime.h>

#define TPB 1024
#define CPT 8                       // cells per thread
#define NBLK 128                    // <=148 SMs -> all co-resident (1 block/SM)
#define NXFIX (TPB * CPT * NBLK)    // 1<<20
#define NSTEPS 32

// Block-edge halos (r,m,E,pad), double-buffered by step parity.
__device__ float4 g_haloL[2][NBLK];   // block b's first cell
__device__ float4 g_haloR[2][NBLK];   // block b's last cell
__device__ unsigned int g_maxbits;    // running max |u|+c (positive float bits)
__device__ unsigned int g_arrive;     // grid barrier arrival counter (blocks)
__device__ volatile unsigned int g_release;  // grid barrier release epoch
__device__ float g_t;
__device__ float g_dtdx;

__global__ void pre_kernel() {
    g_maxbits = 0u;
    g_arrive = 0u;
    g_release = 0u;
    g_t = 0.0f;
}

__device__ __forceinline__ float fsqrt_fast(float x) { return x * rsqrtf(x); }

struct Cell { float r, m, E, u, p, q, H; };

__device__ __forceinline__ Cell derive(float r, float m, float E) {
    Cell c;
    float s = rsqrtf(r);
    float ir = s * s;
    c.r = r; c.m = m; c.E = E;
    c.u = m * ir;
    c.p = 0.4f * (E - 0.5f * m * c.u);
    c.q = r * s;
    c.H = (E + c.p) * ir;
    return c;
}

// Roe flux with Harten entropy fix.
__device__ __forceinline__ float3 roe_flux(const Cell& L, const Cell& R) {
    float rd = __fdividef(1.0f, L.q + R.q);
    float ur = (L.q * L.u + R.q * R.u) * rd;
    float Hr = (L.q * L.H + R.q * R.H) * rd;
    float c2 = fmaxf(0.4f * (Hr - 0.5f * ur * ur), 1e-10f);
    float cinv = rsqrtf(c2);
    float c = c2 * cinv;
    float ic2 = cinv * cinv;
    float e2 = 0.01f * c2;
    float l1 = ur - c, l3 = ur + c;
    float a1 = fsqrt_fast(l1 * l1 + e2);
    float a2 = fsqrt_fast(ur * ur + e2);
    float a3 = fsqrt_fast(l3 * l3 + e2);

    float drho = R.r - L.r, du = R.u - L.u, dp = R.p - L.p;
    float h = 0.5f * ic2;
    float crdu = c * R.r * du;
    float b1 = a1 * ((dp - crdu) * h);
    float b3 = a3 * ((dp + crdu) * h);
    float b2 = a2 * (drho - dp * ic2);
    float uc = ur * c;

    float3 F;
    F.x = 0.5f * (L.m + R.m - (b1 + b2 + b3));
    F.y = 0.5f * ((L.m * L.u + L.p) + (R.m * R.u + R.p)
                  - (b1 * l1 + b2 * ur + b3 * l3));
    F.z = 0.5f * (L.u * (L.E + L.p) + R.u * (R.E + R.p)
                  - (b1 * (Hr - uc) + b2 * (0.5f * ur * ur) + b3 * (Hr + uc)));
    return F;
}

__device__ __forceinline__ float wavespd(float r, float m, float E) {
    float s = rsqrtf(r);
    float ir = s * s;
    float u = m * ir;
    float p = 0.4f * (E - 0.5f * m * u);
    return fabsf(u) + fsqrt_fast(1.4f * p * ir);
}

// tid==0 only, called right after the merged __syncthreads.
// NON-BLOCKING arrive: last-arriving block computes next dt and releases.
__device__ __forceinline__ void block_arrive(const float* tf, unsigned int epoch,
                                             const unsigned int* swm) {
    unsigned int m = swm[0];
#pragma unroll
    for (int w = 1; w < TPB / 32; w++) m = max(m, swm[w]);
    atomicMax(&g_maxbits, m);
    __threadfence();
    unsigned int a = atomicAdd(&g_arrive, 1u);
    if (a == NBLK - 1) {
        float mx = __uint_as_float(g_maxbits);
        float t = *(volatile float*)&g_t;
        float dt = fminf(5e-4f / mx, fmaxf(__ldcg(tf) - t, 0.0f));
        *(volatile float*)&g_t = t + dt;
        *(volatile float*)&g_dtdx = dt * 1000.0f;
        g_maxbits = 0u;
        g_arrive = 0u;
        __threadfence();
        g_release = epoch;
    }
}

__global__ void __launch_bounds__(TPB, 1) euler_kernel(
    const float* __restrict__ rho, const float* __restrict__ uin,
    const float* __restrict__ pin, const float* __restrict__ tf,
    float* __restrict__ out, int n) {
    // Derived state of each thread's LAST cell (written end of prev step).
    __shared__ float sd_r[TPB], sd_m[TPB], sd_E[TPB], sd_u[TPB],
                     sd_p[TPB], sd_q[TPB], sd_H[TPB];
    // Each thread's FIRST flux (left face of its first cell).
    __shared__ float sf_x[TPB], sf_y[TPB], sf_z[TPB];
    __shared__ unsigned int swm[TPB / 32];
    __shared__ float s_dt;

    const int tid = threadIdx.x;
    const int b = blockIdx.x;
    const int i0 = (b * TPB + tid) * CPT;

    float r[CPT], m[CPT], E[CPT];

    // ---- init: primitives -> conserved, halos(parity0), sd, spd, arrive(1) ----
    {
        float spd = 0.0f;
#pragma unroll
        for (int h = 0; h < 2; h++) {
            float4 r4 = *reinterpret_cast<const float4*>(rho + i0 + 4 * h);
            float4 u4 = *reinterpret_cast<const float4*>(uin + i0 + 4 * h);
            float4 p4 = *reinterpret_cast<const float4*>(pin + i0 + 4 * h);
            float rr[4] = {r4.x, r4.y, r4.z, r4.w};
            float uu[4] = {u4.x, u4.y, u4.z, u4.w};
            float pp[4] = {p4.x, p4.y, p4.z, p4.w};
#pragma unroll
            for (int j = 0; j < 4; j++) {
                int k = 4 * h + j;
                r[k] = rr[j];
                m[k] = rr[j] * uu[j];
                E[k] = pp[j] * 2.5f + 0.5f * m[k] * uu[j];
                float s = rsqrtf(rr[j]);
                spd = fmaxf(spd, fabsf(uu[j]) + fsqrt_fast(1.4f * pp[j] * s * s));
            }
        }
        if (tid == 0)
            __stcg(&g_haloL[0][b], make_float4(r[0], m[0], E[0], 0.0f));
        if (tid == TPB - 1) {
            __stcg(&g_haloR[0][b], make_float4(r[CPT - 1], m[CPT - 1], E[CPT - 1], 0.0f));
            __threadfence();
        }
        Cell dl = derive(r[CPT - 1], m[CPT - 1], E[CPT - 1]);
        sd_r[tid] = dl.r; sd_m[tid] = dl.m; sd_E[tid] = dl.E; sd_u[tid] = dl.u;
        sd_p[tid] = dl.p; sd_q[tid] = dl.q; sd_H[tid] = dl.H;
        unsigned int bits = __reduce_max_sync(0xffffffffu, __float_as_uint(spd));
        if ((tid & 31) == 0) swm[tid >> 5] = bits;
        __syncthreads();
        if (tid == 0) block_arrive(tf, 1u, swm);
    }

    // ---- 32 persistent steps ----
    for (int s = 0; s < NSTEPS; s++) {
        const int rb = s & 1;

        // === pre-wait: all dt-independent flux work ===
        Cell d = derive(r[0], m[0], E[0]);
        Cell L;
        if (tid > 0) {
            int j = tid - 1;
            L.r = sd_r[j]; L.m = sd_m[j]; L.E = sd_E[j]; L.u = sd_u[j];
            L.p = sd_p[j]; L.q = sd_q[j]; L.H = sd_H[j];
        } else {
            L = d;   // provisional (exact for b==0; fixed post-wait for b>0)
        }
        float3 Fp = roe_flux(L, d);                 // F0 (provisional for tid0,b>0)
        float3 F0p = Fp;
        sf_x[tid] = Fp.x; sf_y[tid] = Fp.y; sf_z[tid] = Fp.z;

        float dvx[CPT], dvy[CPT], dvz[CPT];
#pragma unroll
        for (int k = 1; k < CPT; k++) {
            Cell dn;
            if (k == CPT - 1) {   // own last-cell derived, cached in shared
                dn.r = sd_r[tid]; dn.m = sd_m[tid]; dn.E = sd_E[tid];
                dn.u = sd_u[tid]; dn.p = sd_p[tid]; dn.q = sd_q[tid];
                dn.H = sd_H[tid];
            } else {
                dn = derive(r[k], m[k], E[k]);
            }
            float3 Fk = roe_flux(d, dn);
            dvx[k - 1] = Fk.x - Fp.x;
            dvy[k - 1] = Fk.y - Fp.y;
            dvz[k - 1] = Fk.z - Fp.z;
            d = dn;
            Fp = Fk;
        }
        // here: Fp = F7, d = derived(cell 7)

        // === wait for this step's dt (overlapped with the work above) ===
        if (tid == 0) {
            while (g_release < (unsigned int)(s + 1)) {}
            __threadfence();
            s_dt = __ldcg(&g_dtdx);
        }
        __syncthreads();
        const float dtdx = s_dt;

        // === post-wait: neighbor flux, edge fixups, update ===
        float3 F8;
        if (tid < TPB - 1) {
            F8.x = sf_x[tid + 1]; F8.y = sf_y[tid + 1]; F8.z = sf_z[tid + 1];
        } else {
            Cell dg;
            if (b < NBLK - 1) {
                float4 gr = __ldcg(&g_haloL[rb][b + 1]);
                dg = derive(gr.x, gr.y, gr.z);
            } else {
                dg = d;   // domain-right replicated ghost
            }
            F8 = roe_flux(d, dg);
        }
        dvx[CPT - 1] = F8.x - Fp.x;
        dvy[CPT - 1] = F8.y - Fp.y;
        dvz[CPT - 1] = F8.z - Fp.z;

        if (tid == 0 && b > 0) {
            float4 gl = __ldcg(&g_haloR[rb][b - 1]);
            Cell dgl = derive(gl.x, gl.y, gl.z);
            Cell d0 = derive(r[0], m[0], E[0]);
            float3 F0n = roe_flux(dgl, d0);
            dvx[0] += F0p.x - F0n.x;
            dvy[0] += F0p.y - F0n.y;
            dvz[0] += F0p.z - F0n.z;
        }

#pragma unroll
        for (int k = 0; k < CPT; k++) {
            r[k] -= dtdx * dvx[k];
            m[k] -= dtdx * dvy[k];
            E[k] -= dtdx * dvz[k];
        }

        if (s + 1 < NSTEPS) {
            // Publish new halos into the other parity buffer.
            if (tid == 0)
                __stcg(&g_haloL[rb ^ 1][b], make_float4(r[0], m[0], E[0], 0.0f));
            if (tid == TPB - 1) {
                __stcg(&g_haloR[rb ^ 1][b],
                       make_float4(r[CPT - 1], m[CPT - 1], E[CPT - 1], 0.0f));
                __threadfence();
            }
            // New-state wavespeed + new derived last cell, one merged sync,
            // then NON-BLOCKING arrive (wait happens next iteration).
            float spd = 0.0f;
#pragma unroll
            for (int k = 0; k < CPT; k++)
                spd = fmaxf(spd, wavespd(r[k], m[k], E[k]));
            Cell dl = derive(r[CPT - 1], m[CPT - 1], E[CPT - 1]);
            sd_r[tid] = dl.r; sd_m[tid] = dl.m; sd_E[tid] = dl.E; sd_u[tid] = dl.u;
            sd_p[tid] = dl.p; sd_q[tid] = dl.q; sd_H[tid] = dl.H;
            unsigned int bits = __reduce_max_sync(0xffffffffu, __float_as_uint(spd));
            if ((tid & 31) == 0) swm[tid >> 5] = bits;
            __syncthreads();
            if (tid == 0) block_arrive(tf, (unsigned int)(s + 2), swm);
        }
    }

    // ---- final: conserved -> primitives, vectorized store ----
#pragma unroll
    for (int h = 0; h < 2; h++) {
        float nr[4], nu[4], np[4];
#pragma unroll
        for (int j = 0; j < 4; j++) {
            int k = 4 * h + j;
            float srr = rsqrtf(r[k]);
            float inr = srr * srr;
            nr[j] = r[k];
            nu[j] = m[k] * inr;
            np[j] = 0.4f * (E[k] - 0.5f * m[k] * nu[j]);
        }
        *reinterpret_cast<float4*>(out + i0 + 4 * h) =
            make_float4(nr[0], nr[1], nr[2], nr[3]);
        *reinterpret_cast<float4*>(out + n + i0 + 4 * h) =
            make_float4(nu[0], nu[1], nu[2], nu[3]);
        *reinterpret_cast<float4*>(out + 2 * n + i0 + 4 * h) =
            make_float4(np[0], np[1], np[2], np[3]);
    }
}

extern "C" void kernel_launch(void* const* d_in, const int* in_sizes, int n_in,
                              void* d_out, int out_size) {
    const float* rho = (const float*)d_in[0];
    const float* u = (const float*)d_in[1];
    const float* p = (const float*)d_in[2];
    const float* tf = (const float*)d_in[3];
    float* out = (float*)d_out;
    int n = in_sizes[0];
    if (n != NXFIX) return;   // problem is fixed at NX = 2^20

    pre_kernel<<<1, 1>>>();
    euler_kernel<<<NBLK, TPB>>>(rho, u, p, tf, out, n);
}

// round 10
// speedup vs baseline: 1.3203x; 1.0514x over previous
#include <cuda_runtime.h>

#define TPB 1024
#define CPT 8                       // cells per thread
#define NBLK 128                    // <=148 SMs -> all co-resident (1 block/SM)
#define NXFIX (TPB * CPT * NBLK)    // 1<<20
#define NSTEPS 32

// Block-edge halos (r,m,E,pad), double-buffered by step parity.
__device__ float4 g_haloL[2][NBLK];   // block b's first cell
__device__ float4 g_haloR[2][NBLK];   // block b's last cell
__device__ unsigned int g_maxbits;    // running max |u|+c (positive float bits)
__device__ unsigned int g_arrive;     // grid barrier arrival counter (blocks)
__device__ volatile unsigned int g_release;  // grid barrier release epoch
__device__ float g_t;
__device__ float g_dtdx;

__global__ void pre_kernel() {
    g_maxbits = 0u;
    g_arrive = 0u;
    g_release = 0u;
    g_t = 0.0f;
}

__device__ __forceinline__ float fsqrt_fast(float x) { return x * rsqrtf(x); }

struct Cell { float r, m, E, u, p, q, H; };

__device__ __forceinline__ Cell derive(float r, float m, float E) {
    Cell c;
    float s = rsqrtf(r);
    float ir = s * s;
    c.r = r; c.m = m; c.E = E;
    c.u = m * ir;
    c.p = 0.4f * (E - 0.5f * m * c.u);
    c.q = r * s;
    c.H = (E + c.p) * ir;
    return c;
}

// Roe flux with Harten entropy fix.
__device__ __forceinline__ float3 roe_flux(const Cell& L, const Cell& R) {
    float rd = __fdividef(1.0f, L.q + R.q);
    float ur = (L.q * L.u + R.q * R.u) * rd;
    float Hr = (L.q * L.H + R.q * R.H) * rd;
    float c2 = fmaxf(0.4f * (Hr - 0.5f * ur * ur), 1e-10f);
    float cinv = rsqrtf(c2);
    float c = c2 * cinv;
    float ic2 = cinv * cinv;
    float e2 = 0.01f * c2;
    float l1 = ur - c, l3 = ur + c;
    float a1 = fsqrt_fast(l1 * l1 + e2);
    float a2 = fsqrt_fast(ur * ur + e2);
    float a3 = fsqrt_fast(l3 * l3 + e2);

    float drho = R.r - L.r, du = R.u - L.u, dp = R.p - L.p;
    float h = 0.5f * ic2;
    float crdu = c * R.r * du;
    float b1 = a1 * ((dp - crdu) * h);
    float b3 = a3 * ((dp + crdu) * h);
    float b2 = a2 * (drho - dp * ic2);
    float uc = ur * c;

    float3 F;
    F.x = 0.5f * (L.m + R.m - (b1 + b2 + b3));
    F.y = 0.5f * ((L.m * L.u + L.p) + (R.m * R.u + R.p)
                  - (b1 * l1 + b2 * ur + b3 * l3));
    F.z = 0.5f * (L.u * (L.E + L.p) + R.u * (R.E + R.p)
                  - (b1 * (Hr - uc) + b2 * (0.5f * ur * ur) + b3 * (Hr + uc)));
    return F;
}

__device__ __forceinline__ float wavespd(float r, float m, float E) {
    float s = rsqrtf(r);
    float ir = s * s;
    float u = m * ir;
    float p = 0.4f * (E - 0.5f * m * u);
    return fabsf(u) + fsqrt_fast(1.4f * p * ir);
}

// tid==0 only, called right after the merged __syncthreads.
// NON-BLOCKING arrive: last-arriving block computes next dt and releases.
__device__ __forceinline__ void block_arrive(const float* tf, unsigned int epoch,
                                             const unsigned int* swm) {
    unsigned int m = swm[0];
#pragma unroll
    for (int w = 1; w < TPB / 32; w++) m = max(m, swm[w]);
    atomicMax(&g_maxbits, m);
    __threadfence();
    unsigned int a = atomicAdd(&g_arrive, 1u);
    if (a == NBLK - 1) {
        float mx = __uint_as_float(g_maxbits);
        float t = *(volatile float*)&g_t;
        float dt = fminf(5e-4f / mx, fmaxf(__ldcg(tf) - t, 0.0f));
        *(volatile float*)&g_t = t + dt;
        *(volatile float*)&g_dtdx = dt * 1000.0f;
        g_maxbits = 0u;
        g_arrive = 0u;
        __threadfence();
        g_release = epoch;
    }
}

__global__ void __launch_bounds__(TPB, 1) euler_kernel(
    const float* __restrict__ rho, const float* __restrict__ uin,
    const float* __restrict__ pin, const float* __restrict__ tf,
    float* __restrict__ out, int n) {
    // Derived state of each thread's LAST cell (written end of prev step).
    __shared__ float sd_r[TPB], sd_m[TPB], sd_E[TPB], sd_u[TPB],
                     sd_p[TPB], sd_q[TPB], sd_H[TPB];
    // Each thread's FIRST flux (left face of its first cell).
    __shared__ float sf_x[TPB], sf_y[TPB], sf_z[TPB];
    __shared__ unsigned int swm[TPB / 32];
    __shared__ float s_dt;

    const int tid = threadIdx.x;
    const int b = blockIdx.x;
    const int i0 = (b * TPB + tid) * CPT;

    float r[CPT], m[CPT], E[CPT];

    // ---- init: primitives -> conserved, halos(parity0), sd, spd, arrive(1) ----
    {
        float spd = 0.0f;
#pragma unroll
        for (int h = 0; h < 2; h++) {
            float4 r4 = *reinterpret_cast<const float4*>(rho + i0 + 4 * h);
            float4 u4 = *reinterpret_cast<const float4*>(uin + i0 + 4 * h);
            float4 p4 = *reinterpret_cast<const float4*>(pin + i0 + 4 * h);
            float rr[4] = {r4.x, r4.y, r4.z, r4.w};
            float uu[4] = {u4.x, u4.y, u4.z, u4.w};
            float pp[4] = {p4.x, p4.y, p4.z, p4.w};
#pragma unroll
            for (int j = 0; j < 4; j++) {
                int k = 4 * h + j;
                r[k] = rr[j];
                m[k] = rr[j] * uu[j];
                E[k] = pp[j] * 2.5f + 0.5f * m[k] * uu[j];
                float s = rsqrtf(rr[j]);
                spd = fmaxf(spd, fabsf(uu[j]) + fsqrt_fast(1.4f * pp[j] * s * s));
            }
        }
        if (tid == 0)
            __stcg(&g_haloL[0][b], make_float4(r[0], m[0], E[0], 0.0f));
        if (tid == TPB - 1) {
            __stcg(&g_haloR[0][b], make_float4(r[CPT - 1], m[CPT - 1], E[CPT - 1], 0.0f));
            __threadfence();
        }
        Cell dl = derive(r[CPT - 1], m[CPT - 1], E[CPT - 1]);
        sd_r[tid] = dl.r; sd_m[tid] = dl.m; sd_E[tid] = dl.E; sd_u[tid] = dl.u;
        sd_p[tid] = dl.p; sd_q[tid] = dl.q; sd_H[tid] = dl.H;
        unsigned int bits = __reduce_max_sync(0xffffffffu, __float_as_uint(spd));
        if ((tid & 31) == 0) swm[tid >> 5] = bits;
        __syncthreads();
        if (tid == 0) block_arrive(tf, 1u, swm);
    }

    // ---- 32 persistent steps ----
    for (int s = 0; s < NSTEPS; s++) {
        const int rb = s & 1;

        // === Phase A (dt-independent): fluxes F0..F4, dv for cells 0..3 ===
        Cell d = derive(r[0], m[0], E[0]);
        Cell L;
        if (tid > 0) {
            int j = tid - 1;
            L.r = sd_r[j]; L.m = sd_m[j]; L.E = sd_E[j]; L.u = sd_u[j];
            L.p = sd_p[j]; L.q = sd_q[j]; L.H = sd_H[j];
        } else {
            L = d;   // provisional (exact for b==0; fixed post-wait for b>0)
        }
        float3 Fp = roe_flux(L, d);            // F0 (provisional for tid0, b>0)
        float3 F0p = Fp;
        sf_x[tid] = Fp.x; sf_y[tid] = Fp.y; sf_z[tid] = Fp.z;

        float dvx[4], dvy[4], dvz[4];
#pragma unroll
        for (int k = 1; k <= 4; k++) {
            Cell dn = derive(r[k], m[k], E[k]);
            float3 Fk = roe_flux(d, dn);
            dvx[k - 1] = Fk.x - Fp.x;
            dvy[k - 1] = Fk.y - Fp.y;
            dvz[k - 1] = Fk.z - Fp.z;
            d = dn;
            Fp = Fk;
        }
        // here: Fp = F4, d = derived(cell 4)

        // === wait for this step's dt (overlapped with Phase A) ===
        if (tid == 0) {
            while (g_release < (unsigned int)(s + 1)) {}
            __threadfence();
            s_dt = __ldcg(&g_dtdx);
        }
        __syncthreads();
        const float dtdx = s_dt;

        // === Phase B: edge fixup, apply dv, stream cells 4..7 ===
        // tid0 fixup must see OLD cell-0 state -> before the update loop.
        if (tid == 0 && b > 0) {
            float4 gl = __ldcg(&g_haloR[rb][b - 1]);
            Cell dgl = derive(gl.x, gl.y, gl.z);
            Cell d0 = derive(r[0], m[0], E[0]);
            float3 F0n = roe_flux(dgl, d0);
            dvx[0] += F0p.x - F0n.x;
            dvy[0] += F0p.y - F0n.y;
            dvz[0] += F0p.z - F0n.z;
        }
#pragma unroll
        for (int k = 0; k < 4; k++) {
            r[k] -= dtdx * dvx[k];
            m[k] -= dtdx * dvy[k];
            E[k] -= dtdx * dvz[k];
        }

        // Stream cells 4..7: derive -> flux -> immediate update (no storage).
#pragma unroll
        for (int k = 5; k < CPT; k++) {
            Cell dn;
            if (k == CPT - 1) {   // own last-cell derived, cached in shared
                dn.r = sd_r[tid]; dn.m = sd_m[tid]; dn.E = sd_E[tid];
                dn.u = sd_u[tid]; dn.p = sd_p[tid]; dn.q = sd_q[tid];
                dn.H = sd_H[tid];
            } else {
                dn = derive(r[k], m[k], E[k]);
            }
            float3 Fk = roe_flux(d, dn);
            r[k - 1] -= dtdx * (Fk.x - Fp.x);
            m[k - 1] -= dtdx * (Fk.y - Fp.y);
            E[k - 1] -= dtdx * (Fk.z - Fp.z);
            d = dn;
            Fp = Fk;
        }

        // F8: right-neighbor's F0 (sf written pre-wait; ordered by wait sync),
        // or ghost roe at block/domain boundary.
        float3 F8;
        if (tid < TPB - 1) {
            F8.x = sf_x[tid + 1]; F8.y = sf_y[tid + 1]; F8.z = sf_z[tid + 1];
        } else {
            Cell dg;
            if (b < NBLK - 1) {
                float4 gr = __ldcg(&g_haloL[rb][b + 1]);
                dg = derive(gr.x, gr.y, gr.z);
            } else {
                dg = d;   // domain-right replicated ghost
            }
            F8 = roe_flux(d, dg);
        }
        r[CPT - 1] -= dtdx * (F8.x - Fp.x);
        m[CPT - 1] -= dtdx * (F8.y - Fp.y);
        E[CPT - 1] -= dtdx * (F8.z - Fp.z);

        if (s + 1 < NSTEPS) {
            // Publish new halos into the other parity buffer.
            if (tid == 0)
                __stcg(&g_haloL[rb ^ 1][b], make_float4(r[0], m[0], E[0], 0.0f));
            if (tid == TPB - 1) {
                __stcg(&g_haloR[rb ^ 1][b],
                       make_float4(r[CPT - 1], m[CPT - 1], E[CPT - 1], 0.0f));
                __threadfence();
            }
            // New-state wavespeed + new derived last cell, one merged sync,
            // then NON-BLOCKING arrive (wait happens next iteration).
            float spd = 0.0f;
#pragma unroll
            for (int k = 0; k < CPT; k++)
                spd = fmaxf(spd, wavespd(r[k], m[k], E[k]));
            Cell dl = derive(r[CPT - 1], m[CPT - 1], E[CPT - 1]);
            sd_r[tid] = dl.r; sd_m[tid] = dl.m; sd_E[tid] = dl.E; sd_u[tid] = dl.u;
            sd_p[tid] = dl.p; sd_q[tid] = dl.q; sd_H[tid] = dl.H;
            unsigned int bits = __reduce_max_sync(0xffffffffu, __float_as_uint(spd));
            if ((tid & 31) == 0) swm[tid >> 5] = bits;
            __syncthreads();
            if (tid == 0) block_arrive(tf, (unsigned int)(s + 2), swm);
        }
    }

    // ---- final: conserved -> primitives, vectorized store ----
#pragma unroll
    for (int h = 0; h < 2; h++) {
        float nr[4], nu[4], np[4];
#pragma unroll
        for (int j = 0; j < 4; j++) {
            int k = 4 * h + j;
            float srr = rsqrtf(r[k]);
            float inr = srr * srr;
            nr[j] = r[k];
            nu[j] = m[k] * inr;
            np[j] = 0.4f * (E[k] - 0.5f * m[k] * nu[j]);
        }
        *reinterpret_cast<float4*>(out + i0 + 4 * h) =
            make_float4(nr[0], nr[1], nr[2], nr[3]);
        *reinterpret_cast<float4*>(out + n + i0 + 4 * h) =
            make_float4(nu[0], nu[1], nu[2], nu[3]);
        *reinterpret_cast<float4*>(out + 2 * n + i0 + 4 * h) =
            make_float4(np[0], np[1], np[2], np[3]);
    }
}

extern "C" void kernel_launch(void* const* d_in, const int* in_sizes, int n_in,
                              void* d_out, int out_size) {
    const float* rho = (const float*)d_in[0];
    const float* u = (const float*)d_in[1];
    const float* p = (const float*)d_in[2];
    const float* tf = (const float*)d_in[3];
    float* out = (float*)d_out;
    int n = in_sizes[0];
    if (n != NXFIX) return;   // problem is fixed at NX = 2^20

    pre_kernel<<<1, 1>>>();
    euler_kernel<<<NBLK, TPB>>>(rho, u, p, tf, out, n);
}

// round 11
// speedup vs baseline: 1.4470x; 1.0960x over previous
#include <cuda_runtime.h>

#define TPB 1024
#define NBLK 148                    // one block per SM, all co-resident
#define NB7 136                     // blocks 0..135: 7 cells/thread; rest: 6
#define NXFIX (1 << 20)             // 136*1024*7 + 12*1024*6 = 1048576
#define NSTEPS 32

// Block-edge halos (r,m,E,pad), double-buffered by step parity.
__device__ float4 g_haloL[2][NBLK];   // block b's first cell
__device__ float4 g_haloR[2][NBLK];   // block b's last cell
__device__ unsigned int g_maxbits;    // running max |u|+c (positive float bits)
__device__ unsigned int g_arrive;     // grid barrier arrival counter (blocks)
__device__ volatile unsigned int g_release;  // grid barrier release epoch
__device__ float g_t;
__device__ float g_dtdx;

__global__ void pre_kernel() {
    g_maxbits = 0u;
    g_arrive = 0u;
    g_release = 0u;
    g_t = 0.0f;
}

__device__ __forceinline__ float fsqrt_fast(float x) { return x * rsqrtf(x); }

struct Cell { float r, m, E, u, p, q, H; };

__device__ __forceinline__ Cell derive(float r, float m, float E) {
    Cell c;
    float s = rsqrtf(r);
    float ir = s * s;
    c.r = r; c.m = m; c.E = E;
    c.u = m * ir;
    c.p = 0.4f * (E - 0.5f * m * c.u);
    c.q = r * s;
    c.H = (E + c.p) * ir;
    return c;
}

// Roe flux with Harten entropy fix.
__device__ __forceinline__ float3 roe_flux(const Cell& L, const Cell& R) {
    float rd = __fdividef(1.0f, L.q + R.q);
    float ur = (L.q * L.u + R.q * R.u) * rd;
    float Hr = (L.q * L.H + R.q * R.H) * rd;
    float c2 = fmaxf(0.4f * (Hr - 0.5f * ur * ur), 1e-10f);
    float cinv = rsqrtf(c2);
    float c = c2 * cinv;
    float ic2 = cinv * cinv;
    float e2 = 0.01f * c2;
    float l1 = ur - c, l3 = ur + c;
    float a1 = fsqrt_fast(l1 * l1 + e2);
    float a2 = fsqrt_fast(ur * ur + e2);
    float a3 = fsqrt_fast(l3 * l3 + e2);

    float drho = R.r - L.r, du = R.u - L.u, dp = R.p - L.p;
    float h = 0.5f * ic2;
    float crdu = c * R.r * du;
    float b1 = a1 * ((dp - crdu) * h);
    float b3 = a3 * ((dp + crdu) * h);
    float b2 = a2 * (drho - dp * ic2);
    float uc = ur * c;

    float3 F;
    F.x = 0.5f * (L.m + R.m - (b1 + b2 + b3));
    F.y = 0.5f * ((L.m * L.u + L.p) + (R.m * R.u + R.p)
                  - (b1 * l1 + b2 * ur + b3 * l3));
    F.z = 0.5f * (L.u * (L.E + L.p) + R.u * (R.E + R.p)
                  - (b1 * (Hr - uc) + b2 * (0.5f * ur * ur) + b3 * (Hr + uc)));
    return F;
}

__device__ __forceinline__ float wavespd(float r, float m, float E) {
    float s = rsqrtf(r);
    float ir = s * s;
    float u = m * ir;
    float p = 0.4f * (E - 0.5f * m * u);
    return fabsf(u) + fsqrt_fast(1.4f * p * ir);
}

// tid==0 only, called right after the merged __syncthreads.
// NON-BLOCKING arrive: last-arriving block computes next dt and releases.
__device__ __forceinline__ void block_arrive(const float* tf, unsigned int epoch,
                                             const unsigned int* swm) {
    unsigned int m = swm[0];
#pragma unroll
    for (int w = 1; w < TPB / 32; w++) m = max(m, swm[w]);
    atomicMax(&g_maxbits, m);
    __threadfence();
    unsigned int a = atomicAdd(&g_arrive, 1u);
    if (a == NBLK - 1) {
        float mx = __uint_as_float(g_maxbits);
        float t = *(volatile float*)&g_t;
        float dt = fminf(5e-4f / mx, fmaxf(__ldcg(tf) - t, 0.0f));
        *(volatile float*)&g_t = t + dt;
        *(volatile float*)&g_dtdx = dt * 1000.0f;
        g_maxbits = 0u;
        g_arrive = 0u;
        __threadfence();
        g_release = epoch;
    }
}

template <int CPT>
__device__ __forceinline__ void run_solver(
    const float* __restrict__ rho, const float* __restrict__ uin,
    const float* __restrict__ pin, const float* __restrict__ tf,
    float* __restrict__ out, int n, int i0, int b,
    float4* sd_a, float4* sd_b,            // derived last cell: (r,m,E,u),(p,q,H,-)
    float* sf_x, float* sf_y, float* sf_z, // each thread's first flux
    unsigned int* swm, float* s_dt) {
    const int tid = threadIdx.x;

    float r[CPT], m[CPT], E[CPT];

    // ---- init: primitives -> conserved, halos(parity0), sd, spd, arrive(1) ----
    {
        float spd = 0.0f;
#pragma unroll
        for (int k = 0; k < CPT; k++) {
            float rr = rho[i0 + k], uu = uin[i0 + k], pp = pin[i0 + k];
            r[k] = rr;
            m[k] = rr * uu;
            E[k] = pp * 2.5f + 0.5f * m[k] * uu;
            float s = rsqrtf(rr);
            spd = fmaxf(spd, fabsf(uu) + fsqrt_fast(1.4f * pp * s * s));
        }
        if (tid == 0)
            __stcg(&g_haloL[0][b], make_float4(r[0], m[0], E[0], 0.0f));
        if (tid == TPB - 1) {
            __stcg(&g_haloR[0][b], make_float4(r[CPT - 1], m[CPT - 1], E[CPT - 1], 0.0f));
            __threadfence();
        }
        Cell dl = derive(r[CPT - 1], m[CPT - 1], E[CPT - 1]);
        sd_a[tid] = make_float4(dl.r, dl.m, dl.E, dl.u);
        sd_b[tid] = make_float4(dl.p, dl.q, dl.H, 0.0f);
        unsigned int bits = __reduce_max_sync(0xffffffffu, __float_as_uint(spd));
        if ((tid & 31) == 0) swm[tid >> 5] = bits;
        __syncthreads();
        if (tid == 0) block_arrive(tf, 1u, swm);
    }

    // ---- 32 persistent steps ----
    for (int s = 0; s < NSTEPS; s++) {
        const int rb = s & 1;

        // === Phase A (dt-independent): fluxes F0..F4, dv for cells 0..3 ===
        Cell d = derive(r[0], m[0], E[0]);
        Cell L;
        if (tid > 0) {
            float4 a = sd_a[tid - 1], bb = sd_b[tid - 1];
            L.r = a.x; L.m = a.y; L.E = a.z; L.u = a.w;
            L.p = bb.x; L.q = bb.y; L.H = bb.z;
        } else {
            L = d;   // provisional (exact for b==0; fixed post-wait for b>0)
        }
        float3 Fp = roe_flux(L, d);            // F0 (provisional for tid0, b>0)
        float3 F0p = Fp;
        sf_x[tid] = Fp.x; sf_y[tid] = Fp.y; sf_z[tid] = Fp.z;

        float dvx[4], dvy[4], dvz[4];
#pragma unroll
        for (int k = 1; k <= 4; k++) {
            Cell dn = derive(r[k], m[k], E[k]);
            float3 Fk = roe_flux(d, dn);
            dvx[k - 1] = Fk.x - Fp.x;
            dvy[k - 1] = Fk.y - Fp.y;
            dvz[k - 1] = Fk.z - Fp.z;
            d = dn;
            Fp = Fk;
        }
        // here: Fp = F4, d = derived(cell 4)

        // === wait for this step's dt (overlapped with Phase A) ===
        if (tid == 0) {
            while (g_release < (unsigned int)(s + 1)) {}
            __threadfence();
            *s_dt = __ldcg(&g_dtdx);
        }
        __syncthreads();
        const float dtdx = *s_dt;

        // === Phase B: edge fixup, apply dv, stream cells 4..CPT-1 ===
        // tid0 fixup must see OLD cell-0 state -> before the update loop.
        if (tid == 0 && b > 0) {
            float4 gl = __ldcg(&g_haloR[rb][b - 1]);
            Cell dgl = derive(gl.x, gl.y, gl.z);
            Cell d0 = derive(r[0], m[0], E[0]);
            float3 F0n = roe_flux(dgl, d0);
            dvx[0] += F0p.x - F0n.x;
            dvy[0] += F0p.y - F0n.y;
            dvz[0] += F0p.z - F0n.z;
        }
#pragma unroll
        for (int k = 0; k < 4; k++) {
            r[k] -= dtdx * dvx[k];
            m[k] -= dtdx * dvy[k];
            E[k] -= dtdx * dvz[k];
        }

        // Stream cells 5..CPT-1: derive -> flux -> immediate update.
#pragma unroll
        for (int k = 5; k < CPT; k++) {
            Cell dn;
            if (k == CPT - 1) {   // own last-cell derived, cached in shared
                float4 a = sd_a[tid], bb = sd_b[tid];
                dn.r = a.x; dn.m = a.y; dn.E = a.z; dn.u = a.w;
                dn.p = bb.x; dn.q = bb.y; dn.H = bb.z;
            } else {
                dn = derive(r[k], m[k], E[k]);
            }
            float3 Fk = roe_flux(d, dn);
            r[k - 1] -= dtdx * (Fk.x - Fp.x);
            m[k - 1] -= dtdx * (Fk.y - Fp.y);
            E[k - 1] -= dtdx * (Fk.z - Fp.z);
            d = dn;
            Fp = Fk;
        }

        // F[CPT]: right-neighbor's F0 (sf written pre-wait; ordered by wait
        // sync), or ghost roe at block/domain boundary.
        float3 F8;
        if (tid < TPB - 1) {
            F8.x = sf_x[tid + 1]; F8.y = sf_y[tid + 1]; F8.z = sf_z[tid + 1];
        } else {
            Cell dg;
            if (b < NBLK - 1) {
                float4 gr = __ldcg(&g_haloL[rb][b + 1]);
                dg = derive(gr.x, gr.y, gr.z);
            } else {
                dg = d;   // domain-right replicated ghost
            }
            F8 = roe_flux(d, dg);
        }
        r[CPT - 1] -= dtdx * (F8.x - Fp.x);
        m[CPT - 1] -= dtdx * (F8.y - Fp.y);
        E[CPT - 1] -= dtdx * (F8.z - Fp.z);

        if (s + 1 < NSTEPS) {
            // Publish new halos into the other parity buffer.
            if (tid == 0)
                __stcg(&g_haloL[rb ^ 1][b], make_float4(r[0], m[0], E[0], 0.0f));
            if (tid == TPB - 1) {
                __stcg(&g_haloR[rb ^ 1][b],
                       make_float4(r[CPT - 1], m[CPT - 1], E[CPT - 1], 0.0f));
                __threadfence();
            }
            // New-state wavespeed + new derived last cell, one merged sync,
            // then NON-BLOCKING arrive (wait happens next iteration).
            float spd = 0.0f;
#pragma unroll
            for (int k = 0; k < CPT; k++)
                spd = fmaxf(spd, wavespd(r[k], m[k], E[k]));
            Cell dl = derive(r[CPT - 1], m[CPT - 1], E[CPT - 1]);
            sd_a[tid] = make_float4(dl.r, dl.m, dl.E, dl.u);
            sd_b[tid] = make_float4(dl.p, dl.q, dl.H, 0.0f);
            unsigned int bits = __reduce_max_sync(0xffffffffu, __float_as_uint(spd));
            if ((tid & 31) == 0) swm[tid >> 5] = bits;
            __syncthreads();
            if (tid == 0) block_arrive(tf, (unsigned int)(s + 2), swm);
        }
    }

    // ---- final: conserved -> primitives ----
#pragma unroll
    for (int k = 0; k < CPT; k++) {
        float srr = rsqrtf(r[k]);
        float inr = srr * srr;
        float nu = m[k] * inr;
        float np = 0.4f * (E[k] - 0.5f * m[k] * nu);
        out[i0 + k] = r[k];
        out[n + i0 + k] = nu;
        out[2 * n + i0 + k] = np;
    }
}

__global__ void __launch_bounds__(TPB, 1) euler_kernel(
    const float* __restrict__ rho, const float* __restrict__ uin,
    const float* __restrict__ pin, const float* __restrict__ tf,
    float* __restrict__ out, int n) {
    __shared__ float4 sd_a[TPB], sd_b[TPB];
    __shared__ float sf_x[TPB], sf_y[TPB], sf_z[TPB];
    __shared__ unsigned int swm[TPB / 32];
    __shared__ float s_dt;

    const int tid = threadIdx.x;
    const int b = blockIdx.x;

    if (b < NB7) {
        int i0 = b * (TPB * 7) + tid * 7;
        run_solver<7>(rho, uin, pin, tf, out, n, i0, b,
                      sd_a, sd_b, sf_x, sf_y, sf_z, swm, &s_dt);
    } else {
        int i0 = NB7 * (TPB * 7) + (b - NB7) * (TPB * 6) + tid * 6;
        run_solver<6>(rho, uin, pin, tf, out, n, i0, b,
                      sd_a, sd_b, sf_x, sf_y, sf_z, swm, &s_dt);
    }
}

extern "C" void kernel_launch(void* const* d_in, const int* in_sizes, int n_in,
                              void* d_out, int out_size) {
    const float* rho = (const float*)d_in[0];
    const float* u = (const float*)d_in[1];
    const float* p = (const float*)d_in[2];
    const float* tf = (const float*)d_in[3];
    float* out = (float*)d_out;
    int n = in_sizes[0];
    if (n != NXFIX) return;   // problem is fixed at NX = 2^20

    pre_kernel<<<1, 1>>>();
    euler_kernel<<<NBLK, TPB>>>(rho, u, p, tf, out, n);
}